// round 13
// baseline (speedup 1.0000x reference)
#include <cuda_runtime.h>
#include <cuda_fp16.h>
#include <cstdint>

// out[256,64] = haar_dwt2(x[256,262144]) @ W[64,262144]^T + b
// Single fused GEMM: W' = adjoint-Haar(W) computed in the B loader.
// mma.sync m16n8k16 fp16, fp32 accum. Grid (148): split-K 148, M=256/CTA.
// 1024 thr = 32 warps (warp tile 16m x 32n), 3-stage ring of 64-col k-blocks.
// Two-stage deterministic split-K reduction (148 = 4 x 37).

#define IN_FEATS (1 << 18)            // 262144
#define BATCH    256
#define NOUT     64
#define KSPLIT   148
#define BK       64                   // fp32 cols per k-block (2 halves of 32)
#define AHALF    32768                // A half-stage: 256 rows x 128 B
#define BSTRIDE  80
#define BHALF    (64 * BSTRIDE)       // 5120
#define HSTG     (AHALF + BHALF)      // 37888
#define STG      (2 * HSTG)           // 75776
#define NSTG     3
#define SMEM_ALLOC (NSTG * STG)       // 227328
#define OUTELEMS (BATCH * NOUT)       // 16384

__device__ float g_part[KSPLIT * OUTELEMS];   // 9.7 MB split-K partials
__device__ float g_part2[4 * OUTELEMS];       // 256 KB stage-1 sums

// ---------------- helpers ----------------
__device__ __forceinline__ uint32_t smem_u32(const void* p) {
    uint32_t a;
    asm("{ .reg .u64 t; cvta.to.shared.u64 t, %1; cvt.u32.u64 %0, t; }"
        : "=r"(a) : "l"(p));
    return a;
}
__device__ __forceinline__ void cp_async16(uint32_t dst, const void* src) {
    asm volatile("cp.async.cg.shared.global [%0], [%1], 16;"
                 :: "r"(dst), "l"(src) : "memory");
}
__device__ __forceinline__ void cp_commit() {
    asm volatile("cp.async.commit_group;" ::: "memory");
}
template <int N>
__device__ __forceinline__ void cp_wait() {
    asm volatile("cp.async.wait_group %0;" :: "n"(N) : "memory");
}
__device__ __forceinline__ void mma_fp16(float* d, const uint32_t* a,
                                         const uint32_t* b) {
    asm volatile(
        "mma.sync.aligned.m16n8k16.row.col.f32.f16.f16.f32 "
        "{%0,%1,%2,%3}, {%4,%5,%6,%7}, {%8,%9}, {%0,%1,%2,%3};"
        : "+f"(d[0]), "+f"(d[1]), "+f"(d[2]), "+f"(d[3])
        : "r"(a[0]), "r"(a[1]), "r"(a[2]), "r"(a[3]), "r"(b[0]), "r"(b[1]));
}
#define LDMX4(r0, r1, r2, r3, addr)                                          \
    asm volatile("ldmatrix.sync.aligned.m8n8.x4.shared.b16 {%0,%1,%2,%3}, [%4];" \
                 : "=r"(r0), "=r"(r1), "=r"(r2), "=r"(r3) : "r"(addr))
__device__ __forceinline__ uint32_t h2u(__half2 h) { return *(uint32_t*)&h; }

// ---------- fused GEMM ----------
// Grid (148). CTA 1024 thr = 32 warps, warp tile 16(m) x 32(n), M=256, N=64.
// k-blocks: 4096 = 100*28 + 48*27.
__global__ __launch_bounds__(1024, 1)
void k_gemm_fused(const float* __restrict__ x, const float* __restrict__ W) {
    extern __shared__ __align__(128) char sm[];
    uint32_t sb = smem_u32(sm);
    int tid = threadIdx.x, l = tid & 31, wid = tid >> 5;
    int ks = blockIdx.x;
    int wm = wid >> 1, wn = wid & 1;          // wm 0..15, wn 0..1

    int nb  = 27 + (ks < 100 ? 1 : 0);
    int jb0 = ks * 27 + (ks < 100 ? ks : 100);
    int k0off = jb0 * BK;

    // ---- A staging (per 32-col half): 2 rows/thread, XOR chunk swizzle ----
    int arow = tid >> 3, ac = tid & 7;        // arow 0..127
    uint32_t swz = (uint32_t)(ac ^ (arow & 7)) << 4;
    const float* a_src[2];
    uint32_t     a_dst[2];
#pragma unroll
    for (int i = 0; i < 2; i++) {
        a_src[i] = x + (size_t)(arow + 128 * i) * IN_FEATS + k0off + ac * 4;
        a_dst[i] = sb + (uint32_t)(arow + 128 * i) * 128 + swz;
    }

    // ---- B fused gather (tid<256): W' row brow, 8 cols per half ----
    bool has_b = (tid < 256);
    int brow = (tid & 255) >> 2, bc = tid & 3;
    const float* wb = W + ((size_t)brow << 18);
    uint32_t b_dst = sb + AHALF + (uint32_t)brow * BSTRIDE + bc * 16;

    float4 wf[2][4];      // [half][band] - short-lived within an iteration
    float  wrs = 1.0f;

#define LDGW(jb)                                                            \
    do {                                                                    \
        int kbase_ = k0off + (jb) * BK;                                     \
        wrs = ((kbase_ >> 8) & 1) ? -1.0f : 1.0f;                           \
        _Pragma("unroll")                                                   \
        for (int h_ = 0; h_ < 2; h_++) {                                    \
            int kk_  = kbase_ + h_ * 32 + bc * 8;                           \
            int c_   = kk_ >> 16;                                           \
            int rr_  = (kk_ >> 8) & 255;                                    \
            int col_ = kk_ & 255;                                           \
            const float* bp_ = wb + (c_ << 16) + ((rr_ >> 1) << 7)          \
                             + (col_ >> 1);                                 \
            wf[h_][0] = *(const float4*)(bp_);                              \
            wf[h_][1] = *(const float4*)(bp_ + 16384);                      \
            wf[h_][2] = *(const float4*)(bp_ + 32768);                      \
            wf[h_][3] = *(const float4*)(bp_ + 49152);                      \
        }                                                                   \
    } while (0)

#define STSB(so)                                                            \
    do {                                                                    \
        _Pragma("unroll")                                                   \
        for (int h_ = 0; h_ < 2; h_++) {                                    \
            float e0 = wf[h_][0].x + wrs * wf[h_][1].x;                     \
            float f0 = wf[h_][2].x + wrs * wf[h_][3].x;                     \
            float e1 = wf[h_][0].y + wrs * wf[h_][1].y;                     \
            float f1 = wf[h_][2].y + wrs * wf[h_][3].y;                     \
            float e2 = wf[h_][0].z + wrs * wf[h_][1].z;                     \
            float f2 = wf[h_][2].z + wrs * wf[h_][3].z;                     \
            float e3 = wf[h_][0].w + wrs * wf[h_][1].w;                     \
            float f3 = wf[h_][2].w + wrs * wf[h_][3].w;                     \
            uint32_t u0 = h2u(__floats2half2_rn(0.5f * (e0 + f0),           \
                                                0.5f * (e0 - f0)));         \
            uint32_t u1 = h2u(__floats2half2_rn(0.5f * (e1 + f1),           \
                                                0.5f * (e1 - f1)));         \
            uint32_t u2 = h2u(__floats2half2_rn(0.5f * (e2 + f2),           \
                                                0.5f * (e2 - f2)));         \
            uint32_t u3 = h2u(__floats2half2_rn(0.5f * (e3 + f3),           \
                                                0.5f * (e3 - f3)));         \
            asm volatile("st.shared.v4.b32 [%0], {%1,%2,%3,%4};"            \
                         :: "r"(b_dst + (so) + (uint32_t)h_ * HSTG),        \
                            "r"(u0), "r"(u1), "r"(u2), "r"(u3));            \
        }                                                                   \
    } while (0)

#define ISSUE_X(jb, so)                                                     \
    do {                                                                    \
        _Pragma("unroll")                                                   \
        for (int h_ = 0; h_ < 2; h_++) {                                    \
            int ko_ = (jb) * BK + h_ * 32;                                  \
            uint32_t ho_ = (so) + (uint32_t)h_ * HSTG;                      \
            _Pragma("unroll")                                               \
            for (int i_ = 0; i_ < 2; i_++)                                  \
                cp_async16(a_dst[i_] + ho_, a_src[i_] + ko_);               \
        }                                                                   \
    } while (0)

    // ---- fragment read bases ----
    int r0 = wm * 16 + (l >> 2), q = (l & 3) * 2;
    int cb = (l >> 1) & 1, rw = r0 & 7;
    uint32_t arb = sb + (uint32_t)r0 * 128 + (l & 1) * 8;
    uint32_t lm_base = sb + AHALF
                     + (uint32_t)(wn * 32 + (l & 7) + ((l >> 4) & 1) * 8) * BSTRIDE
                     + (((l >> 3) & 1) << 4);

    float acc[4][4];
#pragma unroll
    for (int f = 0; f < 4; f++)
#pragma unroll
        for (int i = 0; i < 4; i++) acc[f][i] = 0.0f;

    // ---- prologue: B(0),B(1) staged; x stages 0,1 ----
    if (has_b) {
        LDGW(0); STSB(0);
        LDGW(1); STSB(STG);
    }
    ISSUE_X(0, 0);   cp_commit();
    ISSUE_X(1, STG); cp_commit();

    uint32_t cur = 0, pre = 2 * STG;
    for (int jb = 0; jb < nb; jb++) {
        cp_wait<1>();
        __syncthreads();

        if (jb + 2 < nb) {
            if (has_b) { LDGW(jb + 2); STSB(pre); }
            ISSUE_X(jb + 2, pre);
        }
        cp_commit();

#pragma unroll
        for (int h = 0; h < 2; h++) {
            uint32_t hb = cur + (uint32_t)h * HSTG;
#pragma unroll
            for (int k0 = 0; k0 < 2; k0++) {
                uint32_t c0 = (uint32_t)((cb + 4 * k0) ^ rw) << 4;
                uint32_t c1 = (uint32_t)((cb + 4 * k0 + 2) ^ rw) << 4;
                uint32_t ah[4];
#pragma unroll
                for (int i = 0; i < 4; i++) {
                    uint32_t addr = arb + hb + ((i & 1) ? 1024u : 0u)
                                  + ((i & 2) ? c1 : c0);
                    float2 v;
                    asm volatile("ld.shared.v2.f32 {%0,%1}, [%2];"
                                 : "=f"(v.x), "=f"(v.y) : "r"(addr));
                    ah[i] = h2u(__floats2half2_rn(v.x, v.y));
                }
#pragma unroll
                for (int fp = 0; fp < 2; fp++) {
                    uint32_t b0, b1, b2, b3;
                    LDMX4(b0, b1, b2, b3,
                          lm_base + hb + fp * (16 * BSTRIDE) + k0 * 32);
                    uint32_t bf0[2] = {b0, b1}, bf1[2] = {b2, b3};
                    mma_fp16(acc[fp * 2],     ah, bf0);
                    mma_fp16(acc[fp * 2 + 1], ah, bf1);
                }
            }
        }

        cur += STG; if (cur == NSTG * STG) cur = 0;
        pre += STG; if (pre == NSTG * STG) pre = 0;
    }

    // ---- epilogue: split-K partials ----
    float* pb = g_part + ((size_t)ks * BATCH + r0) * NOUT;
#pragma unroll
    for (int f = 0; f < 4; f++) {
        int n = wn * 32 + f * 8 + q;
        *(float2*)(pb + n)            = make_float2(acc[f][0], acc[f][1]);
        *(float2*)(pb + 8 * NOUT + n) = make_float2(acc[f][2], acc[f][3]);
    }
}

// ---------- reduce stage 1: 148 -> 4 (each block-row sums 37 chunks) ----------
__global__ __launch_bounds__(256) void k_reduce1() {
    int t = blockIdx.x * 256 + threadIdx.x;       // 0..16383
    int p = blockIdx.y;                           // 0..3
    const float* src = g_part + (size_t)p * 37 * OUTELEMS + t;
    float s = 0.0f;
#pragma unroll
    for (int i = 0; i < 37; i++)
        s += src[(size_t)i * OUTELEMS];
    g_part2[p * OUTELEMS + t] = s;
}

// ---------- reduce stage 2: 4 sums + bias ----------
__global__ __launch_bounds__(256) void k_reduce2(const float* __restrict__ bias,
                                                 float* __restrict__ out) {
    int t = blockIdx.x * 256 + threadIdx.x;       // 0..16383
    float s = bias[t & (NOUT - 1)];
    s += g_part2[t];
    s += g_part2[OUTELEMS + t];
    s += g_part2[2 * OUTELEMS + t];
    s += g_part2[3 * OUTELEMS + t];
    out[t] = s;
}

extern "C" void kernel_launch(void* const* d_in, const int* in_sizes, int n_in,
                              void* d_out, int out_size) {
    const float* x = (const float*)d_in[0];
    const float* W = (const float*)d_in[1];
    const float* b = (const float*)d_in[2];

    cudaFuncSetAttribute(k_gemm_fused, cudaFuncAttributeMaxDynamicSharedMemorySize,
                         SMEM_ALLOC);

    k_gemm_fused<<<KSPLIT, 1024, SMEM_ALLOC>>>(x, W);
    k_reduce1<<<dim3(OUTELEMS / 256, 4), 256>>>();
    k_reduce2<<<OUTELEMS / 256, 256>>>(b, (float*)d_out);
}

// round 14
// speedup vs baseline: 1.0706x; 1.0706x over previous
#include <cuda_runtime.h>
#include <cuda_fp16.h>
#include <cstdint>

// out[256,64] = haar_dwt2(x[256,262144]) @ W[64,262144]^T + b
// Single fused GEMM: W' = adjoint-Haar(W) computed in the B loader.
// mma.sync m16n8k16 fp16, fp32 accum. Grid (148), 512 thr = 16 warps:
// warp (wm 0..7, kg 0..1), tile 32m x 64n x 32k (kg = k-half of each
// 64-col staged block -> zero A-fragment duplication). Effective split-K
// = 296; two-stage deterministic reduction (296 = 4 x 74).

#define IN_FEATS (1 << 18)            // 262144
#define BATCH    256
#define NOUT     64
#define KSPLIT   148
#define KPARTS   (2 * KSPLIT)         // 296 partial sets
#define BK       64                   // fp32 cols per k-block (2 halves of 32)
#define AHALF    32768                // A half-stage: 256 rows x 128 B
#define BSTRIDE  80
#define BHALF    (64 * BSTRIDE)       // 5120
#define HSTG     (AHALF + BHALF)      // 37888
#define STG      (2 * HSTG)           // 75776
#define NSTG     3
#define SMEM_ALLOC (NSTG * STG)       // 227328
#define OUTELEMS (BATCH * NOUT)       // 16384

__device__ float g_part[KPARTS * OUTELEMS];   // 19.4 MB split-K partials
__device__ float g_part2[4 * OUTELEMS];       // 256 KB stage-1 sums

// ---------------- helpers ----------------
__device__ __forceinline__ uint32_t smem_u32(const void* p) {
    uint32_t a;
    asm("{ .reg .u64 t; cvta.to.shared.u64 t, %1; cvt.u32.u64 %0, t; }"
        : "=r"(a) : "l"(p));
    return a;
}
__device__ __forceinline__ void cp_async16(uint32_t dst, const void* src) {
    asm volatile("cp.async.cg.shared.global [%0], [%1], 16;"
                 :: "r"(dst), "l"(src) : "memory");
}
__device__ __forceinline__ void cp_commit() {
    asm volatile("cp.async.commit_group;" ::: "memory");
}
template <int N>
__device__ __forceinline__ void cp_wait() {
    asm volatile("cp.async.wait_group %0;" :: "n"(N) : "memory");
}
__device__ __forceinline__ void mma_fp16(float* d, const uint32_t* a,
                                         const uint32_t* b) {
    asm volatile(
        "mma.sync.aligned.m16n8k16.row.col.f32.f16.f16.f32 "
        "{%0,%1,%2,%3}, {%4,%5,%6,%7}, {%8,%9}, {%0,%1,%2,%3};"
        : "+f"(d[0]), "+f"(d[1]), "+f"(d[2]), "+f"(d[3])
        : "r"(a[0]), "r"(a[1]), "r"(a[2]), "r"(a[3]), "r"(b[0]), "r"(b[1]));
}
#define LDMX4(r0, r1, r2, r3, addr)                                          \
    asm volatile("ldmatrix.sync.aligned.m8n8.x4.shared.b16 {%0,%1,%2,%3}, [%4];" \
                 : "=r"(r0), "=r"(r1), "=r"(r2), "=r"(r3) : "r"(addr))
__device__ __forceinline__ uint32_t h2u(__half2 h) { return *(uint32_t*)&h; }

// ---------- fused GEMM ----------
// Grid (148). k-blocks: 4096 = 100*28 + 48*27.
__global__ __launch_bounds__(512, 1)
void k_gemm_fused(const float* __restrict__ x, const float* __restrict__ W) {
    extern __shared__ __align__(128) char sm[];
    uint32_t sb = smem_u32(sm);
    int tid = threadIdx.x, l = tid & 31, wid = tid >> 5;
    int ks = blockIdx.x;
    int wm = wid >> 1, kg = wid & 1;          // wm 0..7, kg 0..1

    int nb  = 27 + (ks < 100 ? 1 : 0);
    int jb0 = ks * 27 + (ks < 100 ? ks : 100);
    int k0off = jb0 * BK;

    // ---- A staging (per 32-col half): 4 rows/thread, XOR chunk swizzle ----
    int arow = tid >> 3, ac = tid & 7;        // arow 0..63
    uint32_t swz = (uint32_t)(ac ^ (arow & 7)) << 4;
    const float* a_src[4];
    uint32_t     a_dst[4];
#pragma unroll
    for (int i = 0; i < 4; i++) {
        a_src[i] = x + (size_t)(arow + 64 * i) * IN_FEATS + k0off + ac * 4;
        a_dst[i] = sb + (uint32_t)(arow + 64 * i) * 128 + swz;
    }

    // ---- B fused gather (tid<256): W' row brow, 8 cols per half ----
    bool has_b = (tid < 256);
    int brow = (tid & 255) >> 2, bc = tid & 3;
    const float* wb = W + ((size_t)brow << 18);
    uint32_t b_dst = sb + AHALF + (uint32_t)brow * BSTRIDE + bc * 16;

    float4 wf[4];         // one half's 4 bands (short-lived)

#define GSTB_H(jb, h_, so)                                                  \
    do {                                                                    \
        int kbase_ = k0off + (jb) * BK;                                     \
        float wrs_ = ((kbase_ >> 8) & 1) ? -1.0f : 1.0f;                    \
        int kk_  = kbase_ + (h_) * 32 + bc * 8;                             \
        const float* bp_ = wb + ((kk_ >> 16) << 16)                         \
                         + ((((kk_ >> 8) & 255) >> 1) << 7)                 \
                         + ((kk_ & 255) >> 1);                              \
        wf[0] = *(const float4*)(bp_);                                      \
        wf[1] = *(const float4*)(bp_ + 16384);                              \
        wf[2] = *(const float4*)(bp_ + 32768);                              \
        wf[3] = *(const float4*)(bp_ + 49152);                              \
        float e0 = wf[0].x + wrs_ * wf[1].x, f0 = wf[2].x + wrs_ * wf[3].x; \
        float e1 = wf[0].y + wrs_ * wf[1].y, f1 = wf[2].y + wrs_ * wf[3].y; \
        float e2 = wf[0].z + wrs_ * wf[1].z, f2 = wf[2].z + wrs_ * wf[3].z; \
        float e3 = wf[0].w + wrs_ * wf[1].w, f3 = wf[2].w + wrs_ * wf[3].w; \
        uint32_t u0 = h2u(__floats2half2_rn(0.5f * (e0 + f0),               \
                                            0.5f * (e0 - f0)));             \
        uint32_t u1 = h2u(__floats2half2_rn(0.5f * (e1 + f1),               \
                                            0.5f * (e1 - f1)));             \
        uint32_t u2 = h2u(__floats2half2_rn(0.5f * (e2 + f2),               \
                                            0.5f * (e2 - f2)));             \
        uint32_t u3 = h2u(__floats2half2_rn(0.5f * (e3 + f3),               \
                                            0.5f * (e3 - f3)));             \
        asm volatile("st.shared.v4.b32 [%0], {%1,%2,%3,%4};"                \
                     :: "r"(b_dst + (so) + (uint32_t)(h_) * HSTG),          \
                        "r"(u0), "r"(u1), "r"(u2), "r"(u3));                \
    } while (0)

#define ISSUE_X(jb, so)                                                     \
    do {                                                                    \
        _Pragma("unroll")                                                   \
        for (int h_ = 0; h_ < 2; h_++) {                                    \
            int ko_ = (jb) * BK + h_ * 32;                                  \
            uint32_t ho_ = (so) + (uint32_t)h_ * HSTG;                      \
            _Pragma("unroll")                                               \
            for (int i_ = 0; i_ < 4; i_++)                                  \
                cp_async16(a_dst[i_] + ho_, a_src[i_] + ko_);               \
        }                                                                   \
    } while (0)

    // ---- fragment read bases ----
    int r0 = wm * 32 + (l >> 2), q = (l & 3) * 2;
    int cb = (l >> 1) & 1, rw = r0 & 7;
    uint32_t arb = sb + (uint32_t)r0 * 128 + (l & 1) * 8;
    // B ldmatrix base: rows (l&7) + ((l>>4)&1)*8  (+ fp*16), chunk (l>>3)&1
    uint32_t lm_base = sb + AHALF
                     + (uint32_t)((l & 7) + ((l >> 4) & 1) * 8) * BSTRIDE
                     + (((l >> 3) & 1) << 4);

    float acc[8][4];
#pragma unroll
    for (int f = 0; f < 8; f++)
#pragma unroll
        for (int i = 0; i < 4; i++) acc[f][i] = 0.0f;

    // ---- prologue ----
    if (has_b) {
        GSTB_H(0, 0, 0);   GSTB_H(0, 1, 0);
        GSTB_H(1, 0, STG); GSTB_H(1, 1, STG);
    }
    ISSUE_X(0, 0);   cp_commit();
    ISSUE_X(1, STG); cp_commit();

    uint32_t cur = 0, pre = 2 * STG;
    for (int jb = 0; jb < nb; jb++) {
        cp_wait<1>();
        __syncthreads();

        if (jb + 2 < nb) {
            if (has_b) { GSTB_H(jb + 2, 0, pre); GSTB_H(jb + 2, 1, pre); }
            ISSUE_X(jb + 2, pre);
        }
        cp_commit();

        uint32_t hb = cur + (uint32_t)kg * HSTG;   // this warp's k-half
#pragma unroll
        for (int k0 = 0; k0 < 2; k0++) {
            uint32_t c0 = (uint32_t)((cb + 4 * k0) ^ rw) << 4;
            uint32_t c1 = (uint32_t)((cb + 4 * k0 + 2) ^ rw) << 4;
            uint32_t ah[2][4];
#pragma unroll
            for (int mf = 0; mf < 2; mf++) {
                uint32_t base = arb + hb + (uint32_t)mf * 2048;
#pragma unroll
                for (int i = 0; i < 4; i++) {
                    uint32_t addr = base + ((i & 1) ? 1024u : 0u)
                                  + ((i & 2) ? c1 : c0);
                    float2 v;
                    asm volatile("ld.shared.v2.f32 {%0,%1}, [%2];"
                                 : "=f"(v.x), "=f"(v.y) : "r"(addr));
                    ah[mf][i] = h2u(__floats2half2_rn(v.x, v.y));
                }
            }
#pragma unroll
            for (int fp = 0; fp < 4; fp++) {
                uint32_t b0, b1, b2, b3;
                LDMX4(b0, b1, b2, b3,
                      lm_base + hb + fp * (16 * BSTRIDE) + k0 * 32);
                uint32_t bf0[2] = {b0, b1}, bf1[2] = {b2, b3};
#pragma unroll
                for (int mf = 0; mf < 2; mf++) {
                    // acc index: n-frag = fp*2 + j; m handled by mf row offset
                    mma_fp16(acc[fp * 2]     + 0, ah[mf], bf0);
                    mma_fp16(acc[fp * 2 + 1] + 0, ah[mf], bf1);
                    // NOTE: mf=0 and mf=1 write the same acc? NO - see below
                }
            }
            // The mf loop above must use distinct accumulators; restructure:
        }

        cur += STG; if (cur == NSTG * STG) cur = 0;
        pre += STG; if (pre == NSTG * STG) pre = 0;
    }

    // ---- epilogue ----
    // (replaced below - see corrected kernel body)
}

// ======================================================================
// The kernel above had an acc-indexing flaw in the draft; the REAL kernel
// used is k_gemm_fused2 below with acc[2][8][4] (mf x nfrag).
// ======================================================================
__global__ __launch_bounds__(512, 1)
void k_gemm_fused2(const float* __restrict__ x, const float* __restrict__ W) {
    extern __shared__ __align__(128) char sm[];
    uint32_t sb = smem_u32(sm);
    int tid = threadIdx.x, l = tid & 31, wid = tid >> 5;
    int ks = blockIdx.x;
    int wm = wid >> 1, kg = wid & 1;

    int nb  = 27 + (ks < 100 ? 1 : 0);
    int jb0 = ks * 27 + (ks < 100 ? ks : 100);
    int k0off = jb0 * BK;

    int arow = tid >> 3, ac = tid & 7;
    uint32_t swz = (uint32_t)(ac ^ (arow & 7)) << 4;
    const float* a_src[4];
    uint32_t     a_dst[4];
#pragma unroll
    for (int i = 0; i < 4; i++) {
        a_src[i] = x + (size_t)(arow + 64 * i) * IN_FEATS + k0off + ac * 4;
        a_dst[i] = sb + (uint32_t)(arow + 64 * i) * 128 + swz;
    }

    bool has_b = (tid < 256);
    int brow = (tid & 255) >> 2, bc = tid & 3;
    const float* wb = W + ((size_t)brow << 18);
    uint32_t b_dst = sb + AHALF + (uint32_t)brow * BSTRIDE + bc * 16;
    float4 wf[4];

    int r0 = wm * 32 + (l >> 2), q = (l & 3) * 2;
    int cb = (l >> 1) & 1, rw = r0 & 7;
    uint32_t arb = sb + (uint32_t)r0 * 128 + (l & 1) * 8;
    uint32_t lm_base = sb + AHALF
                     + (uint32_t)((l & 7) + ((l >> 4) & 1) * 8) * BSTRIDE
                     + (((l >> 3) & 1) << 4);

    float acc[2][8][4];
#pragma unroll
    for (int m = 0; m < 2; m++)
#pragma unroll
        for (int f = 0; f < 8; f++)
#pragma unroll
            for (int i = 0; i < 4; i++) acc[m][f][i] = 0.0f;

    if (has_b) {
        GSTB_H(0, 0, 0);   GSTB_H(0, 1, 0);
        GSTB_H(1, 0, STG); GSTB_H(1, 1, STG);
    }
    ISSUE_X(0, 0);   cp_commit();
    ISSUE_X(1, STG); cp_commit();

    uint32_t cur = 0, pre = 2 * STG;
    for (int jb = 0; jb < nb; jb++) {
        cp_wait<1>();
        __syncthreads();

        if (jb + 2 < nb) {
            if (has_b) { GSTB_H(jb + 2, 0, pre); GSTB_H(jb + 2, 1, pre); }
            ISSUE_X(jb + 2, pre);
        }
        cp_commit();

        uint32_t hb = cur + (uint32_t)kg * HSTG;
#pragma unroll
        for (int k0 = 0; k0 < 2; k0++) {
            uint32_t c0 = (uint32_t)((cb + 4 * k0) ^ rw) << 4;
            uint32_t c1 = (uint32_t)((cb + 4 * k0 + 2) ^ rw) << 4;
            uint32_t ah[2][4];
#pragma unroll
            for (int mf = 0; mf < 2; mf++) {
                uint32_t base = arb + hb + (uint32_t)mf * 2048;
#pragma unroll
                for (int i = 0; i < 4; i++) {
                    uint32_t addr = base + ((i & 1) ? 1024u : 0u)
                                  + ((i & 2) ? c1 : c0);
                    float2 v;
                    asm volatile("ld.shared.v2.f32 {%0,%1}, [%2];"
                                 : "=f"(v.x), "=f"(v.y) : "r"(addr));
                    ah[mf][i] = h2u(__floats2half2_rn(v.x, v.y));
                }
            }
#pragma unroll
            for (int fp = 0; fp < 4; fp++) {
                uint32_t b0, b1, b2, b3;
                LDMX4(b0, b1, b2, b3,
                      lm_base + hb + fp * (16 * BSTRIDE) + k0 * 32);
                uint32_t bf0[2] = {b0, b1}, bf1[2] = {b2, b3};
#pragma unroll
                for (int mf = 0; mf < 2; mf++) {
                    mma_fp16(acc[mf][fp * 2],     ah[mf], bf0);
                    mma_fp16(acc[mf][fp * 2 + 1], ah[mf], bf1);
                }
            }
        }

        cur += STG; if (cur == NSTG * STG) cur = 0;
        pre += STG; if (pre == NSTG * STG) pre = 0;
    }

    // epilogue: partial set = ks*2 + kg
#pragma unroll
    for (int mf = 0; mf < 2; mf++) {
        int gm = wm * 32 + mf * 16 + (l >> 2);
        float* pb = g_part + ((size_t)(ks * 2 + kg) * BATCH + gm) * NOUT;
#pragma unroll
        for (int f = 0; f < 8; f++) {
            int n = f * 8 + q;
            *(float2*)(pb + n) =
                make_float2(acc[mf][f][0], acc[mf][f][1]);
            *(float2*)(pb + 8 * NOUT + n) =
                make_float2(acc[mf][f][2], acc[mf][f][3]);
        }
    }
}

// ---------- reduce stage 1: 296 -> 4 (each sums 74 chunks) ----------
__global__ __launch_bounds__(256) void k_reduce1() {
    int t = blockIdx.x * 256 + threadIdx.x;
    int p = blockIdx.y;                           // 0..3
    const float* src = g_part + (size_t)p * 74 * OUTELEMS + t;
    float s = 0.0f;
#pragma unroll 2
    for (int i = 0; i < 74; i++)
        s += src[(size_t)i * OUTELEMS];
    g_part2[p * OUTELEMS + t] = s;
}

// ---------- reduce stage 2: 4 sums + bias ----------
__global__ __launch_bounds__(256) void k_reduce2(const float* __restrict__ bias,
                                                 float* __restrict__ out) {
    int t = blockIdx.x * 256 + threadIdx.x;
    float s = bias[t & (NOUT - 1)];
    s += g_part2[t];
    s += g_part2[OUTELEMS + t];
    s += g_part2[2 * OUTELEMS + t];
    s += g_part2[3 * OUTELEMS + t];
    out[t] = s;
}

extern "C" void kernel_launch(void* const* d_in, const int* in_sizes, int n_in,
                              void* d_out, int out_size) {
    const float* x = (const float*)d_in[0];
    const float* W = (const float*)d_in[1];
    const float* b = (const float*)d_in[2];

    cudaFuncSetAttribute(k_gemm_fused2, cudaFuncAttributeMaxDynamicSharedMemorySize,
                         SMEM_ALLOC);

    k_gemm_fused2<<<KSPLIT, 512, SMEM_ALLOC>>>(x, W);
    k_reduce1<<<dim3(OUTELEMS / 256, 4), 256>>>();
    k_reduce2<<<OUTELEMS / 256, 256>>>(b, (float*)d_out);
}

// round 15
// speedup vs baseline: 1.1835x; 1.1054x over previous
#include <cuda_runtime.h>
#include <cuda_fp16.h>
#include <cstdint>

// out[256,64] = haar_dwt2(x[256,262144]) @ W[64,262144]^T + b
// Single fused GEMM: W' = adjoint-Haar(W) computed in the B loader.
// mma.sync m16n8k16 fp16, fp32 accum. Grid (148), 512 thr = 16 warps:
// warp (wm 0..7, kg 0..1), tile 32m x 64n x 32k (kg = k-half of each
// staged 64-col block -> zero A-fragment duplication). Effective split-K
// = 296; two-stage deterministic reduction (296 = 8 x 37).

#define IN_FEATS (1 << 18)            // 262144
#define BATCH    256
#define NOUT     64
#define KSPLIT   148
#define KPARTS   (2 * KSPLIT)         // 296 partial sets
#define BK       64                   // fp32 cols per k-block (2 halves of 32)
#define AHALF    32768                // A half-stage: 256 rows x 128 B
#define BSTRIDE  80
#define BHALF    (64 * BSTRIDE)       // 5120
#define HSTG     (AHALF + BHALF)      // 37888
#define STG      (2 * HSTG)           // 75776
#define NSTG     3
#define SMEM_ALLOC (NSTG * STG)       // 227328
#define OUTELEMS (BATCH * NOUT)       // 16384

__device__ float g_part[KPARTS * OUTELEMS];   // 19.4 MB split-K partials
__device__ float g_part2[8 * OUTELEMS];       // 512 KB stage-1 sums

// ---------------- helpers ----------------
__device__ __forceinline__ uint32_t smem_u32(const void* p) {
    uint32_t a;
    asm("{ .reg .u64 t; cvta.to.shared.u64 t, %1; cvt.u32.u64 %0, t; }"
        : "=r"(a) : "l"(p));
    return a;
}
__device__ __forceinline__ void cp_async16(uint32_t dst, const void* src) {
    asm volatile("cp.async.cg.shared.global [%0], [%1], 16;"
                 :: "r"(dst), "l"(src) : "memory");
}
__device__ __forceinline__ void cp_commit() {
    asm volatile("cp.async.commit_group;" ::: "memory");
}
template <int N>
__device__ __forceinline__ void cp_wait() {
    asm volatile("cp.async.wait_group %0;" :: "n"(N) : "memory");
}
__device__ __forceinline__ void mma_fp16(float* d, const uint32_t* a,
                                         const uint32_t* b) {
    asm volatile(
        "mma.sync.aligned.m16n8k16.row.col.f32.f16.f16.f32 "
        "{%0,%1,%2,%3}, {%4,%5,%6,%7}, {%8,%9}, {%0,%1,%2,%3};"
        : "+f"(d[0]), "+f"(d[1]), "+f"(d[2]), "+f"(d[3])
        : "r"(a[0]), "r"(a[1]), "r"(a[2]), "r"(a[3]), "r"(b[0]), "r"(b[1]));
}
#define LDMX4(r0, r1, r2, r3, addr)                                          \
    asm volatile("ldmatrix.sync.aligned.m8n8.x4.shared.b16 {%0,%1,%2,%3}, [%4];" \
                 : "=r"(r0), "=r"(r1), "=r"(r2), "=r"(r3) : "r"(addr))
__device__ __forceinline__ uint32_t h2u(__half2 h) { return *(uint32_t*)&h; }

#define GSTB_H(jb, h_, so)                                                  \
    do {                                                                    \
        int kbase_ = k0off + (jb) * BK;                                     \
        float wrs_ = ((kbase_ >> 8) & 1) ? -1.0f : 1.0f;                    \
        int kk_  = kbase_ + (h_) * 32 + bc * 8;                             \
        const float* bp_ = wb + ((kk_ >> 16) << 16)                         \
                         + ((((kk_ >> 8) & 255) >> 1) << 7)                 \
                         + ((kk_ & 255) >> 1);                              \
        wf[0] = *(const float4*)(bp_);                                      \
        wf[1] = *(const float4*)(bp_ + 16384);                              \
        wf[2] = *(const float4*)(bp_ + 32768);                              \
        wf[3] = *(const float4*)(bp_ + 49152);                              \
        float e0 = wf[0].x + wrs_ * wf[1].x, f0 = wf[2].x + wrs_ * wf[3].x; \
        float e1 = wf[0].y + wrs_ * wf[1].y, f1 = wf[2].y + wrs_ * wf[3].y; \
        float e2 = wf[0].z + wrs_ * wf[1].z, f2 = wf[2].z + wrs_ * wf[3].z; \
        float e3 = wf[0].w + wrs_ * wf[1].w, f3 = wf[2].w + wrs_ * wf[3].w; \
        uint32_t u0 = h2u(__floats2half2_rn(0.5f * (e0 + f0),               \
                                            0.5f * (e0 - f0)));             \
        uint32_t u1 = h2u(__floats2half2_rn(0.5f * (e1 + f1),               \
                                            0.5f * (e1 - f1)));             \
        uint32_t u2 = h2u(__floats2half2_rn(0.5f * (e2 + f2),               \
                                            0.5f * (e2 - f2)));             \
        uint32_t u3 = h2u(__floats2half2_rn(0.5f * (e3 + f3),               \
                                            0.5f * (e3 - f3)));             \
        asm volatile("st.shared.v4.b32 [%0], {%1,%2,%3,%4};"                \
                     :: "r"(b_dst + (so) + (uint32_t)(h_) * HSTG),          \
                        "r"(u0), "r"(u1), "r"(u2), "r"(u3));                \
    } while (0)

#define ISSUE_X(jb, so)                                                     \
    do {                                                                    \
        _Pragma("unroll")                                                   \
        for (int h_ = 0; h_ < 2; h_++) {                                    \
            int ko_ = (jb) * BK + h_ * 32;                                  \
            uint32_t ho_ = (so) + (uint32_t)h_ * HSTG;                      \
            _Pragma("unroll")                                               \
            for (int i_ = 0; i_ < 4; i_++)                                  \
                cp_async16(a_dst[i_] + ho_, a_src[i_] + ko_);               \
        }                                                                   \
    } while (0)

// ---------- fused GEMM ----------
// Grid (148). k-blocks: 4096 = 100*28 + 48*27.
__global__ __launch_bounds__(512, 1)
void k_gemm_fused2(const float* __restrict__ x, const float* __restrict__ W) {
    extern __shared__ __align__(128) char sm[];
    uint32_t sb = smem_u32(sm);
    int tid = threadIdx.x, l = tid & 31, wid = tid >> 5;
    int ks = blockIdx.x;
    int wm = wid >> 1, kg = wid & 1;

    int nb  = 27 + (ks < 100 ? 1 : 0);
    int jb0 = ks * 27 + (ks < 100 ? ks : 100);
    int k0off = jb0 * BK;

    int arow = tid >> 3, ac = tid & 7;
    uint32_t swz = (uint32_t)(ac ^ (arow & 7)) << 4;
    const float* a_src[4];
    uint32_t     a_dst[4];
#pragma unroll
    for (int i = 0; i < 4; i++) {
        a_src[i] = x + (size_t)(arow + 64 * i) * IN_FEATS + k0off + ac * 4;
        a_dst[i] = sb + (uint32_t)(arow + 64 * i) * 128 + swz;
    }

    bool has_b = (tid < 256);
    int brow = (tid & 255) >> 2, bc = tid & 3;
    const float* wb = W + ((size_t)brow << 18);
    uint32_t b_dst = sb + AHALF + (uint32_t)brow * BSTRIDE + bc * 16;
    float4 wf[4];

    int r0 = wm * 32 + (l >> 2), q = (l & 3) * 2;
    int cb = (l >> 1) & 1, rw = r0 & 7;
    uint32_t arb = sb + (uint32_t)r0 * 128 + (l & 1) * 8;
    uint32_t lm_base = sb + AHALF
                     + (uint32_t)((l & 7) + ((l >> 4) & 1) * 8) * BSTRIDE
                     + (((l >> 3) & 1) << 4);

    float acc[2][8][4];
#pragma unroll
    for (int m = 0; m < 2; m++)
#pragma unroll
        for (int f = 0; f < 8; f++)
#pragma unroll
            for (int i = 0; i < 4; i++) acc[m][f][i] = 0.0f;

    if (has_b) {
        GSTB_H(0, 0, 0);   GSTB_H(0, 1, 0);
        GSTB_H(1, 0, STG); GSTB_H(1, 1, STG);
    }
    ISSUE_X(0, 0);   cp_commit();
    ISSUE_X(1, STG); cp_commit();

    uint32_t cur = 0, pre = 2 * STG;
    for (int jb = 0; jb < nb; jb++) {
        cp_wait<1>();
        __syncthreads();

        if (jb + 2 < nb) {
            if (has_b) { GSTB_H(jb + 2, 0, pre); GSTB_H(jb + 2, 1, pre); }
            ISSUE_X(jb + 2, pre);
        }
        cp_commit();

        uint32_t hb = cur + (uint32_t)kg * HSTG;
#pragma unroll
        for (int k0 = 0; k0 < 2; k0++) {
            uint32_t c0 = (uint32_t)((cb + 4 * k0) ^ rw) << 4;
            uint32_t c1 = (uint32_t)((cb + 4 * k0 + 2) ^ rw) << 4;
            uint32_t ah[2][4];
#pragma unroll
            for (int mf = 0; mf < 2; mf++) {
                uint32_t base = arb + hb + (uint32_t)mf * 2048;
#pragma unroll
                for (int i = 0; i < 4; i++) {
                    uint32_t addr = base + ((i & 1) ? 1024u : 0u)
                                  + ((i & 2) ? c1 : c0);
                    float2 v;
                    asm volatile("ld.shared.v2.f32 {%0,%1}, [%2];"
                                 : "=f"(v.x), "=f"(v.y) : "r"(addr));
                    ah[mf][i] = h2u(__floats2half2_rn(v.x, v.y));
                }
            }
#pragma unroll
            for (int fp = 0; fp < 4; fp++) {
                uint32_t b0, b1, b2, b3;
                LDMX4(b0, b1, b2, b3,
                      lm_base + hb + fp * (16 * BSTRIDE) + k0 * 32);
                uint32_t bf0[2] = {b0, b1}, bf1[2] = {b2, b3};
#pragma unroll
                for (int mf = 0; mf < 2; mf++) {
                    mma_fp16(acc[mf][fp * 2],     ah[mf], bf0);
                    mma_fp16(acc[mf][fp * 2 + 1], ah[mf], bf1);
                }
            }
        }

        cur += STG; if (cur == NSTG * STG) cur = 0;
        pre += STG; if (pre == NSTG * STG) pre = 0;
    }

    // epilogue: partial set = ks*2 + kg
#pragma unroll
    for (int mf = 0; mf < 2; mf++) {
        int gm = wm * 32 + mf * 16 + (l >> 2);
        float* pb = g_part + ((size_t)(ks * 2 + kg) * BATCH + gm) * NOUT;
#pragma unroll
        for (int f = 0; f < 8; f++) {
            int n = f * 8 + q;
            *(float2*)(pb + n) =
                make_float2(acc[mf][f][0], acc[mf][f][1]);
            *(float2*)(pb + 8 * NOUT + n) =
                make_float2(acc[mf][f][2], acc[mf][f][3]);
        }
    }
}

// ---------- reduce stage 1: 296 -> 8 (each sums 37 chunks, full MLP) ----------
__global__ __launch_bounds__(256) void k_reduce1() {
    int t = blockIdx.x * 256 + threadIdx.x;       // 0..16383
    int p = blockIdx.y;                           // 0..7
    const float* src = g_part + (size_t)p * 37 * OUTELEMS + t;
    float s = 0.0f;
#pragma unroll
    for (int i = 0; i < 37; i++)
        s += src[(size_t)i * OUTELEMS];
    g_part2[p * OUTELEMS + t] = s;
}

// ---------- reduce stage 2: 8 sums + bias ----------
__global__ __launch_bounds__(256) void k_reduce2(const float* __restrict__ bias,
                                                 float* __restrict__ out) {
    int t = blockIdx.x * 256 + threadIdx.x;       // 0..16383
    float s = bias[t & (NOUT - 1)];
#pragma unroll
    for (int p = 0; p < 8; p++)
        s += g_part2[p * OUTELEMS + t];
    out[t] = s;
}

extern "C" void kernel_launch(void* const* d_in, const int* in_sizes, int n_in,
                              void* d_out, int out_size) {
    const float* x = (const float*)d_in[0];
    const float* W = (const float*)d_in[1];
    const float* b = (const float*)d_in[2];

    cudaFuncSetAttribute(k_gemm_fused2, cudaFuncAttributeMaxDynamicSharedMemorySize,
                         SMEM_ALLOC);

    k_gemm_fused2<<<KSPLIT, 512, SMEM_ALLOC>>>(x, W);
    k_reduce1<<<dim3(OUTELEMS / 256, 8), 256>>>();
    k_reduce2<<<OUTELEMS / 256, 256>>>(b, (float*)d_out);
}

// round 16
// speedup vs baseline: 1.1913x; 1.0066x over previous
#include <cuda_runtime.h>
#include <cuda_fp16.h>
#include <cstdint>

// out[256,64] = haar_dwt2(x[256,262144]) @ W[64,262144]^T + b
// Single fused GEMM: W' = adjoint-Haar(W) computed in the B loader
// (gather spread over all 512 threads, LD/ST phases split around the
// A cp.async issue to hide LDG latency).
// mma.sync m16n8k16 fp16, fp32 accum. Grid (148), 512 thr = 16 warps:
// warp (wm 0..7, kg 0..1), tile 32m x 64n x 32k. Effective split-K = 296;
// two-stage deterministic reduction (296 = 8 x 37).

#define IN_FEATS (1 << 18)            // 262144
#define BATCH    256
#define NOUT     64
#define KSPLIT   148
#define KPARTS   (2 * KSPLIT)         // 296 partial sets
#define BK       64                   // fp32 cols per k-block (2 halves of 32)
#define AHALF    32768                // A half-stage: 256 rows x 128 B
#define BSTRIDE  80
#define BHALF    (64 * BSTRIDE)       // 5120
#define HSTG     (AHALF + BHALF)      // 37888
#define STG      (2 * HSTG)           // 75776
#define NSTG     3
#define SMEM_ALLOC (NSTG * STG)       // 227328
#define OUTELEMS (BATCH * NOUT)       // 16384

__device__ float g_part[KPARTS * OUTELEMS];   // 19.4 MB split-K partials
__device__ float g_part2[8 * OUTELEMS];       // 512 KB stage-1 sums

// ---------------- helpers ----------------
__device__ __forceinline__ uint32_t smem_u32(const void* p) {
    uint32_t a;
    asm("{ .reg .u64 t; cvta.to.shared.u64 t, %1; cvt.u32.u64 %0, t; }"
        : "=r"(a) : "l"(p));
    return a;
}
__device__ __forceinline__ void cp_async16(uint32_t dst, const void* src) {
    asm volatile("cp.async.cg.shared.global [%0], [%1], 16;"
                 :: "r"(dst), "l"(src) : "memory");
}
__device__ __forceinline__ void cp_commit() {
    asm volatile("cp.async.commit_group;" ::: "memory");
}
template <int N>
__device__ __forceinline__ void cp_wait() {
    asm volatile("cp.async.wait_group %0;" :: "n"(N) : "memory");
}
__device__ __forceinline__ void mma_fp16(float* d, const uint32_t* a,
                                         const uint32_t* b) {
    asm volatile(
        "mma.sync.aligned.m16n8k16.row.col.f32.f16.f16.f32 "
        "{%0,%1,%2,%3}, {%4,%5,%6,%7}, {%8,%9}, {%0,%1,%2,%3};"
        : "+f"(d[0]), "+f"(d[1]), "+f"(d[2]), "+f"(d[3])
        : "r"(a[0]), "r"(a[1]), "r"(a[2]), "r"(a[3]), "r"(b[0]), "r"(b[1]));
}
#define LDMX4(r0, r1, r2, r3, addr)                                          \
    asm volatile("ldmatrix.sync.aligned.m8n8.x4.shared.b16 {%0,%1,%2,%3}, [%4];" \
                 : "=r"(r0), "=r"(r1), "=r"(r2), "=r"(r3) : "r"(addr))
__device__ __forceinline__ uint32_t h2u(__half2 h) { return *(uint32_t*)&h; }

// ---- B gather: each of 512 threads handles ONE k-half (hh = tid>>8) ----
// LD phase: 4 band LDG.128 into wf;  ST phase: butterfly + one STS.128.
#define GSTB_LD(jb)                                                         \
    do {                                                                    \
        int kbase_ = k0off + (jb) * BK;                                     \
        wrs = ((kbase_ >> 8) & 1) ? -1.0f : 1.0f;                           \
        int kk_ = kbase_ + hh * 32 + bc * 8;                                \
        const float* bp_ = wb + ((kk_ >> 16) << 16)                         \
                         + ((((kk_ >> 8) & 255) >> 1) << 7)                 \
                         + ((kk_ & 255) >> 1);                              \
        wf[0] = *(const float4*)(bp_);                                      \
        wf[1] = *(const float4*)(bp_ + 16384);                              \
        wf[2] = *(const float4*)(bp_ + 32768);                              \
        wf[3] = *(const float4*)(bp_ + 49152);                              \
    } while (0)

#define GSTB_ST(so)                                                         \
    do {                                                                    \
        float e0 = wf[0].x + wrs * wf[1].x, f0 = wf[2].x + wrs * wf[3].x;   \
        float e1 = wf[0].y + wrs * wf[1].y, f1 = wf[2].y + wrs * wf[3].y;   \
        float e2 = wf[0].z + wrs * wf[1].z, f2 = wf[2].z + wrs * wf[3].z;   \
        float e3 = wf[0].w + wrs * wf[1].w, f3 = wf[2].w + wrs * wf[3].w;   \
        uint32_t u0 = h2u(__floats2half2_rn(0.5f * (e0 + f0),               \
                                            0.5f * (e0 - f0)));             \
        uint32_t u1 = h2u(__floats2half2_rn(0.5f * (e1 + f1),               \
                                            0.5f * (e1 - f1)));             \
        uint32_t u2 = h2u(__floats2half2_rn(0.5f * (e2 + f2),               \
                                            0.5f * (e2 - f2)));             \
        uint32_t u3 = h2u(__floats2half2_rn(0.5f * (e3 + f3),               \
                                            0.5f * (e3 - f3)));             \
        asm volatile("st.shared.v4.b32 [%0], {%1,%2,%3,%4};"                \
                     :: "r"(b_dst + (so)),                                  \
                        "r"(u0), "r"(u1), "r"(u2), "r"(u3));                \
    } while (0)

#define ISSUE_X(jb, so)                                                     \
    do {                                                                    \
        _Pragma("unroll")                                                   \
        for (int h_ = 0; h_ < 2; h_++) {                                    \
            int ko_ = (jb) * BK + h_ * 32;                                  \
            uint32_t ho_ = (so) + (uint32_t)h_ * HSTG;                      \
            _Pragma("unroll")                                               \
            for (int i_ = 0; i_ < 4; i_++)                                  \
                cp_async16(a_dst[i_] + ho_, a_src[i_] + ko_);               \
        }                                                                   \
    } while (0)

// ---------- fused GEMM ----------
// Grid (148). k-blocks: 4096 = 100*28 + 48*27.
__global__ __launch_bounds__(512, 1)
void k_gemm_fused2(const float* __restrict__ x, const float* __restrict__ W) {
    extern __shared__ __align__(128) char sm[];
    uint32_t sb = smem_u32(sm);
    int tid = threadIdx.x, l = tid & 31, wid = tid >> 5;
    int ks = blockIdx.x;
    int wm = wid >> 1, kg = wid & 1;

    int nb  = 27 + (ks < 100 ? 1 : 0);
    int jb0 = ks * 27 + (ks < 100 ? ks : 100);
    int k0off = jb0 * BK;

    int arow = tid >> 3, ac = tid & 7;
    uint32_t swz = (uint32_t)(ac ^ (arow & 7)) << 4;
    const float* a_src[4];
    uint32_t     a_dst[4];
#pragma unroll
    for (int i = 0; i < 4; i++) {
        a_src[i] = x + (size_t)(arow + 64 * i) * IN_FEATS + k0off + ac * 4;
        a_dst[i] = sb + (uint32_t)(arow + 64 * i) * 128 + swz;
    }

    // B gather ownership: hh = k-half, e = (brow, bc) within half
    int hh = tid >> 8;                       // 0 or 1
    int e  = tid & 255;
    int brow = e >> 2, bc = e & 3;
    const float* wb = W + ((size_t)brow << 18);
    uint32_t b_dst = sb + AHALF + (uint32_t)brow * BSTRIDE + bc * 16
                   + (uint32_t)hh * HSTG;
    float4 wf[4];
    float  wrs = 1.0f;

    int r0 = wm * 32 + (l >> 2), q = (l & 3) * 2;
    int cb = (l >> 1) & 1, rw = r0 & 7;
    uint32_t arb = sb + (uint32_t)r0 * 128 + (l & 1) * 8;
    uint32_t lm_base = sb + AHALF
                     + (uint32_t)((l & 7) + ((l >> 4) & 1) * 8) * BSTRIDE
                     + (((l >> 3) & 1) << 4);

    float acc[2][8][4];
#pragma unroll
    for (int m = 0; m < 2; m++)
#pragma unroll
        for (int f = 0; f < 8; f++)
#pragma unroll
            for (int i = 0; i < 4; i++) acc[m][f][i] = 0.0f;

    // ---- prologue ----
    GSTB_LD(0); GSTB_ST(0);
    GSTB_LD(1); GSTB_ST(STG);
    ISSUE_X(0, 0);   cp_commit();
    ISSUE_X(1, STG); cp_commit();

    uint32_t cur = 0, pre = 2 * STG;
    for (int jb = 0; jb < nb; jb++) {
        cp_wait<1>();
        __syncthreads();

        if (jb + 2 < nb) {
            GSTB_LD(jb + 2);        // 4 LDG.128 in flight
            ISSUE_X(jb + 2, pre);   // independent cp.asyncs issue meanwhile
            cp_commit();
            GSTB_ST(pre);           // butterfly consumes LDG results
        } else {
            cp_commit();
        }

        uint32_t hb = cur + (uint32_t)kg * HSTG;
#pragma unroll
        for (int k0 = 0; k0 < 2; k0++) {
            uint32_t c0 = (uint32_t)((cb + 4 * k0) ^ rw) << 4;
            uint32_t c1 = (uint32_t)((cb + 4 * k0 + 2) ^ rw) << 4;
            uint32_t ah[2][4];
#pragma unroll
            for (int mf = 0; mf < 2; mf++) {
                uint32_t base = arb + hb + (uint32_t)mf * 2048;
#pragma unroll
                for (int i = 0; i < 4; i++) {
                    uint32_t addr = base + ((i & 1) ? 1024u : 0u)
                                  + ((i & 2) ? c1 : c0);
                    float2 v;
                    asm volatile("ld.shared.v2.f32 {%0,%1}, [%2];"
                                 : "=f"(v.x), "=f"(v.y) : "r"(addr));
                    ah[mf][i] = h2u(__floats2half2_rn(v.x, v.y));
                }
            }
#pragma unroll
            for (int fp = 0; fp < 4; fp++) {
                uint32_t b0, b1, b2, b3;
                LDMX4(b0, b1, b2, b3,
                      lm_base + hb + fp * (16 * BSTRIDE) + k0 * 32);
                uint32_t bf0[2] = {b0, b1}, bf1[2] = {b2, b3};
#pragma unroll
                for (int mf = 0; mf < 2; mf++) {
                    mma_fp16(acc[mf][fp * 2],     ah[mf], bf0);
                    mma_fp16(acc[mf][fp * 2 + 1], ah[mf], bf1);
                }
            }
        }

        cur += STG; if (cur == NSTG * STG) cur = 0;
        pre += STG; if (pre == NSTG * STG) pre = 0;
    }

    // epilogue: partial set = ks*2 + kg
#pragma unroll
    for (int mf = 0; mf < 2; mf++) {
        int gm = wm * 32 + mf * 16 + (l >> 2);
        float* pb = g_part + ((size_t)(ks * 2 + kg) * BATCH + gm) * NOUT;
#pragma unroll
        for (int f = 0; f < 8; f++) {
            int n = f * 8 + q;
            *(float2*)(pb + n) =
                make_float2(acc[mf][f][0], acc[mf][f][1]);
            *(float2*)(pb + 8 * NOUT + n) =
                make_float2(acc[mf][f][2], acc[mf][f][3]);
        }
    }
}

// ---------- reduce stage 1: 296 -> 8 (each sums 37 chunks, full MLP) ----------
__global__ __launch_bounds__(256) void k_reduce1() {
    int t = blockIdx.x * 256 + threadIdx.x;       // 0..16383
    int p = blockIdx.y;                           // 0..7
    const float* src = g_part + (size_t)p * 37 * OUTELEMS + t;
    float s = 0.0f;
#pragma unroll
    for (int i = 0; i < 37; i++)
        s += src[(size_t)i * OUTELEMS];
    g_part2[p * OUTELEMS + t] = s;
}

// ---------- reduce stage 2: 8 sums + bias ----------
__global__ __launch_bounds__(256) void k_reduce2(const float* __restrict__ bias,
                                                 float* __restrict__ out) {
    int t = blockIdx.x * 256 + threadIdx.x;       // 0..16383
    float s = bias[t & (NOUT - 1)];
#pragma unroll
    for (int p = 0; p < 8; p++)
        s += g_part2[p * OUTELEMS + t];
    out[t] = s;
}

extern "C" void kernel_launch(void* const* d_in, const int* in_sizes, int n_in,
                              void* d_out, int out_size) {
    const float* x = (const float*)d_in[0];
    const float* W = (const float*)d_in[1];
    const float* b = (const float*)d_in[2];

    cudaFuncSetAttribute(k_gemm_fused2, cudaFuncAttributeMaxDynamicSharedMemorySize,
                         SMEM_ALLOC);

    k_gemm_fused2<<<KSPLIT, 512, SMEM_ALLOC>>>(x, W);
    k_reduce1<<<dim3(OUTELEMS / 256, 8), 256>>>();
    k_reduce2<<<OUTELEMS / 256, 256>>>(b, (float*)d_out);
}